// round 15
// baseline (speedup 1.0000x reference)
#include <cuda_runtime.h>
#include <cuda_fp16.h>
#include <cstdint>

// Problem constants: B=512, T=2048, I=4, H=100, O=1
#define HDIM     100
#define TLEN     2048
#define BLOCK_T  128    // one 4-warp group; 4 batch chains per warp
#define NBLOCKS  128    // 4 batches per CTA -> 512
#define PADH     128    // h row stride in smem (floats); pad stays 0
#define KH       52     // columns per K-half (100 padded to 104)
#define PADHS    104    // fp16 trajectory row stride (208 B = 13 x 16 B)

// hidden-state trajectory: [b][t][104] fp16. Pad [100..104) stays zero
// (zero-initialized module storage, never written) and is dotted with
// zero weights in proj_kernel.
__device__ __half Hs[(size_t)512 * TLEN * PADHS];

// ---- packed fp32x2 ops (Blackwell FFMA2 path, only reachable via PTX) ----
__device__ __forceinline__ unsigned long long ffma2(unsigned long long a,
                                                    unsigned long long b,
                                                    unsigned long long c) {
    unsigned long long d;
    asm("fma.rn.f32x2 %0, %1, %2, %3;" : "=l"(d) : "l"(a), "l"(b), "l"(c));
    return d;
}
__device__ __forceinline__ unsigned long long fadd2(unsigned long long a,
                                                    unsigned long long b) {
    unsigned long long d;
    asm("add.rn.f32x2 %0, %1, %2;" : "=l"(d) : "l"(a), "l"(b));
    return d;
}
__device__ __forceinline__ float hsum2(unsigned long long a) {
    unsigned int lo, hi;
    asm("mov.b64 {%0, %1}, %2;" : "=r"(lo), "=r"(hi) : "l"(a));
    return __uint_as_float(lo) + __uint_as_float(hi);
}

// tanh(x) = 1 - 2/(exp2(2*log2e*x)+1)  (validated rel_err ~1e-6 over 2048 steps)
__device__ __forceinline__ float fast_tanh(float x) {
    float e, r;
    asm("ex2.approx.f32 %0, %1;" : "=f"(e) : "f"(x * 2.8853900817779268f));
    asm("rcp.approx.f32 %0, %1;" : "=f"(r) : "f"(e + 1.0f));
    return fmaf(-2.0f, r, 1.0f);
}

// ============================================================================
// Kernel 1: recurrence with FOUR independent batch chains per warp.
// W_hh registers (104) shared by all 4 chains; per-chain state is just
// accumulators + x. All latency hiding is intra-warp (phase-lock immune).
// ============================================================================
__global__ void __launch_bounds__(BLOCK_T, 1)
crnn_step_kernel(const float* __restrict__ x,      // [512, 2048, 4]
                 const float* __restrict__ W_ih,   // [100, 4]
                 const float* __restrict__ W_hh)   // [100, 100]
{
    // hbuf[buf][local batch][PADH]
    __shared__ __align__(16) float hbuf[2][4][PADH];

    const int tid   = threadIdx.x;
    const int lane  = tid & 31;
    const int wig   = tid >> 5;                 // warp 0..3
    const int praw  = wig * 16 + (lane >> 1);   // row-pair index 0..63
    const int j     = lane & 1;                 // K-half 0/1
    const bool active = (praw < 50);
    const int pc    = active ? praw : 49;       // clamp for safe loads
    const int row0  = 2 * pc;
    const int own   = row0 + j;                 // row this thread finalizes
    const int bgb   = blockIdx.x * 4;           // first batch of this CTA

    // zero h buffers (h0 = 0; pad [100,128) stays 0 forever)
    for (int i = tid; i < 2 * 4 * PADH; i += BLOCK_T)
        ((float*)hbuf)[i] = 0.0f;

    // ---- W_hh: 2 rows x 52-col half -> 104 regs (shared by all 4 chains) --
    unsigned long long w0[26], w1[26];
    {
        const ulonglong2* r0p =
            reinterpret_cast<const ulonglong2*>(W_hh + row0 * HDIM + KH * j);
        const ulonglong2* r1p =
            reinterpret_cast<const ulonglong2*>(W_hh + (row0 + 1) * HDIM + KH * j);
        #pragma unroll
        for (int k = 0; k < 13; k++) {
            ulonglong2 v = r0p[k];
            w0[2 * k] = v.x;  w0[2 * k + 1] = v.y;
        }
        #pragma unroll
        for (int k = 0; k < 12; k++) {
            ulonglong2 v = r1p[k];
            w1[2 * k] = v.x;  w1[2 * k + 1] = v.y;
        }
        // row 99's upper half, last pair: would read past W_hh; matching h
        // values are the zero pad, so zero weights are exact.
        if (pc == 49 && j == 1) {
            w1[24] = 0ull; w1[25] = 0ull;
        } else {
            ulonglong2 v = r1p[12];
            w1[24] = v.x; w1[25] = v.y;
        }
    }

    const float4 wih = *reinterpret_cast<const float4*>(W_ih + own * 4);

    const float4* xp[4];
    __half* hs[4];
    #pragma unroll
    for (int b = 0; b < 4; b++) {
        xp[b] = reinterpret_cast<const float4*>(x) + (size_t)(bgb + b) * TLEN;
        hs[b] = Hs + (size_t)(bgb + b) * TLEN * PADHS + own;
    }

    __syncthreads();                     // init barrier

    float4 xc[4];
    #pragma unroll
    for (int b = 0; b < 4; b++) xc[b] = xp[b][0];

    int cur = 0;

    #pragma unroll 1
    for (int t = 0; t < TLEN; t++) {
        const int tn = (t < TLEN - 1) ? (t + 1) : t;
        float4 xn0 = xp[0][tn];
        float4 xn1 = xp[1][tn];
        float4 xn2 = xp[2][tn];
        float4 xn3 = xp[3][tn];

        // input projections (independent of h)
        float xpj[4];
        #pragma unroll
        for (int b = 0; b < 4; b++) {
            float v = xc[b].x * wih.x;
            v = fmaf(xc[b].y, wih.y, v);
            v = fmaf(xc[b].z, wih.z, v);
            xpj[b] = fmaf(xc[b].w, wih.w, v);
        }

        // four interleaved matvecs over this thread's K-half
        // acc[b][0..3] = {row0 even, row0 odd, row1 even, row1 odd}
        unsigned long long acc[4][4];
        #pragma unroll
        for (int b = 0; b < 4; b++)
            acc[b][0] = acc[b][1] = acc[b][2] = acc[b][3] = 0ull;

        const ulonglong2* hv0 =
            reinterpret_cast<const ulonglong2*>(&hbuf[cur][0][KH * j]);
        const ulonglong2* hv1 =
            reinterpret_cast<const ulonglong2*>(&hbuf[cur][1][KH * j]);
        const ulonglong2* hv2 =
            reinterpret_cast<const ulonglong2*>(&hbuf[cur][2][KH * j]);
        const ulonglong2* hv3 =
            reinterpret_cast<const ulonglong2*>(&hbuf[cur][3][KH * j]);

        #pragma unroll
        for (int k = 0; k < 13; k++) {
            const unsigned long long wk0 = w0[2 * k], wk1 = w0[2 * k + 1];
            const unsigned long long wk2 = w1[2 * k], wk3 = w1[2 * k + 1];
            ulonglong2 h0 = hv0[k];
            ulonglong2 h1 = hv1[k];
            ulonglong2 h2 = hv2[k];
            ulonglong2 h3 = hv3[k];
            acc[0][0] = ffma2(h0.x, wk0, acc[0][0]);
            acc[1][0] = ffma2(h1.x, wk0, acc[1][0]);
            acc[2][0] = ffma2(h2.x, wk0, acc[2][0]);
            acc[3][0] = ffma2(h3.x, wk0, acc[3][0]);
            acc[0][1] = ffma2(h0.y, wk1, acc[0][1]);
            acc[1][1] = ffma2(h1.y, wk1, acc[1][1]);
            acc[2][1] = ffma2(h2.y, wk1, acc[2][1]);
            acc[3][1] = ffma2(h3.y, wk1, acc[3][1]);
            acc[0][2] = ffma2(h0.x, wk2, acc[0][2]);
            acc[1][2] = ffma2(h1.x, wk2, acc[1][2]);
            acc[2][2] = ffma2(h2.x, wk2, acc[2][2]);
            acc[3][2] = ffma2(h3.x, wk2, acc[3][2]);
            acc[0][3] = ffma2(h0.y, wk3, acc[0][3]);
            acc[1][3] = ffma2(h1.y, wk3, acc[1][3]);
            acc[2][3] = ffma2(h2.y, wk3, acc[2][3]);
            acc[3][3] = ffma2(h3.y, wk3, acc[3][3]);
        }

        // per-chain: half-dot sums, partner-lane combine, tanh
        float hn[4];
        #pragma unroll
        for (int b = 0; b < 4; b++) {
            float s0 = hsum2(fadd2(acc[b][0], acc[b][1]));  // row0 half
            float s1 = hsum2(fadd2(acc[b][2], acc[b][3]));  // row1 half
            float u0 = s0 + __shfl_xor_sync(0xFFFFFFFFu, s0, 1);
            float u1 = s1 + __shfl_xor_sync(0xFFFFFFFFu, s1, 1);
            hn[b] = fast_tanh((j ? u1 : u0) + xpj[b]);
        }

        // publish h_{t+1} (smem) + fp16 trajectory (gmem, dead-end):
        // both PRE-barrier — absorbed into barrier wait (R12 vs R13 finding)
        if (active) {
            hbuf[cur ^ 1][0][own] = hn[0];
            hbuf[cur ^ 1][1][own] = hn[1];
            hbuf[cur ^ 1][2][own] = hn[2];
            hbuf[cur ^ 1][3][own] = hn[3];
            hs[0][0] = __float2half_rn(hn[0]);
            hs[1][0] = __float2half_rn(hn[1]);
            hs[2][0] = __float2half_rn(hn[2]);
            hs[3][0] = __float2half_rn(hn[3]);
        }
        #pragma unroll
        for (int b = 0; b < 4; b++) hs[b] += PADHS;

        __syncthreads();                 // step barrier (whole CTA = 4 warps)

        cur ^= 1;
        xc[0] = xn0; xc[1] = xn1; xc[2] = xn2; xc[3] = xn3;
    }
}

// ============================================================================
// Kernel 2: out[b,t] = W_fc . h[b,t] + b_fc.  THREAD per output: 13 LDG.128
// over the 208 B fp16 row (13-deep MLP), weights broadcast from smem,
// 8 parallel fp32 accumulators, no shuffles. DRAM-bound on 218 MB.
// ============================================================================
#define K2_BLOCK 256
#define K2_GRID  4096   // 4096 * 256 = 1,048,576 = 512 * 2048 outputs exactly

__global__ void __launch_bounds__(K2_BLOCK)
proj_kernel(const float* __restrict__ W_fc,   // [1, 100]
            const float* __restrict__ b_fc,   // [1]
            float* __restrict__ out)          // [512*2048]
{
    // weights as 104 floats (pad [100,104) = 0): 26 float4 broadcasts
    __shared__ __align__(16) float wsm[PADHS];
    {
        const int tt = threadIdx.x;
        if (tt < PADHS)
            wsm[tt] = (tt < HDIM) ? W_fc[tt] : 0.0f;
    }
    __syncthreads();

    const int bt = blockIdx.x * K2_BLOCK + threadIdx.x;   // one output/thread
    const float bias = b_fc[0];

    const uint4* hp = reinterpret_cast<const uint4*>(Hs + (size_t)bt * PADHS);
    const float4* wp = reinterpret_cast<const float4*>(wsm);

    float acc0 = 0.f, acc1 = 0.f, acc2 = 0.f, acc3 = 0.f;
    float acc4 = 0.f, acc5 = 0.f, acc6 = 0.f, acc7 = 0.f;

    #pragma unroll
    for (int k = 0; k < 13; k++) {
        uint4 v = hp[k];                        // 8 fp16 values
        float4 wa = wp[2 * k];
        float4 wb = wp[2 * k + 1];
        float2 f0 = __half22float2(*reinterpret_cast<const __half2*>(&v.x));
        float2 f1 = __half22float2(*reinterpret_cast<const __half2*>(&v.y));
        float2 f2 = __half22float2(*reinterpret_cast<const __half2*>(&v.z));
        float2 f3 = __half22float2(*reinterpret_cast<const __half2*>(&v.w));
        acc0 = fmaf(f0.x, wa.x, acc0);
        acc1 = fmaf(f0.y, wa.y, acc1);
        acc2 = fmaf(f1.x, wa.z, acc2);
        acc3 = fmaf(f1.y, wa.w, acc3);
        acc4 = fmaf(f2.x, wb.x, acc4);
        acc5 = fmaf(f2.y, wb.y, acc5);
        acc6 = fmaf(f3.x, wb.z, acc6);
        acc7 = fmaf(f3.y, wb.w, acc7);
    }

    const float s = ((acc0 + acc1) + (acc2 + acc3)) +
                    ((acc4 + acc5) + (acc6 + acc7));
    out[bt] = s + bias;
}

extern "C" void kernel_launch(void* const* d_in, const int* in_sizes, int n_in,
                              void* d_out, int out_size) {
    const float* x    = (const float*)d_in[0];  // [512,2048,4]
    const float* W_ih = (const float*)d_in[1];  // [100,4]
    const float* W_hh = (const float*)d_in[2];  // [100,100]
    const float* W_fc = (const float*)d_in[3];  // [1,100]
    const float* b_fc = (const float*)d_in[4];  // [1]
    float* out = (float*)d_out;                 // [512,2048,1]

    crnn_step_kernel<<<NBLOCKS, BLOCK_T>>>(x, W_ih, W_hh);
    proj_kernel<<<K2_GRID, K2_BLOCK>>>(W_fc, b_fc, out);
}

// round 16
// speedup vs baseline: 1.1331x; 1.1331x over previous
#include <cuda_runtime.h>
#include <cuda_fp16.h>
#include <cstdint>

// Problem constants: B=512, T=2048, I=4, H=100, O=1
#define HDIM     100
#define TLEN     2048
#define BLOCK_T  256
#define NBLOCKS  128    // 4 batches per CTA (2 groups x 2 batches) -> 512
#define PADH     128    // h row stride in smem (floats); pad stays 0
#define KH       52     // columns per K-half (100 padded to 104)
#define PADHS    104    // fp16 trajectory row stride (208 B = 13 x 16 B)

// hidden-state trajectory: [b][t][104] fp16. Pad [100..104) stays zero
// (zero-initialized module storage, never written) and is dotted with
// zero weights in proj_kernel.
__device__ __half Hs[(size_t)512 * TLEN * PADHS];

// ---- packed fp32x2 ops (Blackwell FFMA2 path, only reachable via PTX) ----
__device__ __forceinline__ unsigned long long ffma2(unsigned long long a,
                                                    unsigned long long b,
                                                    unsigned long long c) {
    unsigned long long d;
    asm("fma.rn.f32x2 %0, %1, %2, %3;" : "=l"(d) : "l"(a), "l"(b), "l"(c));
    return d;
}
__device__ __forceinline__ unsigned long long fadd2(unsigned long long a,
                                                    unsigned long long b) {
    unsigned long long d;
    asm("add.rn.f32x2 %0, %1, %2;" : "=l"(d) : "l"(a), "l"(b));
    return d;
}
__device__ __forceinline__ float hsum2(unsigned long long a) {
    unsigned int lo, hi;
    asm("mov.b64 {%0, %1}, %2;" : "=r"(lo), "=r"(hi) : "l"(a));
    return __uint_as_float(lo) + __uint_as_float(hi);
}

// tanh(x) = 1 - 2/(exp2(2*log2e*x)+1)  (validated rel_err ~1e-6 over 2048 steps)
__device__ __forceinline__ float fast_tanh(float x) {
    float e, r;
    asm("ex2.approx.f32 %0, %1;" : "=f"(e) : "f"(x * 2.8853900817779268f));
    asm("rcp.approx.f32 %0, %1;" : "=f"(r) : "f"(e + 1.0f));
    return fmaf(-2.0f, r, 1.0f);
}

__device__ __forceinline__ void group_bar(int id) {
    asm volatile("bar.sync %0, %1;" :: "r"(id), "n"(128) : "memory");
}

// ============================================================================
// Kernel 1: the recurrence — R12 structure VERBATIM (best measured: ~1029us).
// 128-thread group advances TWO batches with shared W_hh registers (two
// independent dependency chains per warp). Trajectory STGs PRE-barrier:
// absorbed by the barrier wait (R12 vs R13 A/B: +-75us on this placement).
// ============================================================================
__global__ void __launch_bounds__(BLOCK_T, 1)
crnn_step_kernel(const float* __restrict__ x,      // [512, 2048, 4]
                 const float* __restrict__ W_ih,   // [100, 4]
                 const float* __restrict__ W_hh)   // [100, 100]
{
    // hbuf[buf][group][local batch][PADH]
    __shared__ __align__(16) float hbuf[2][2][2][PADH];

    const int tid   = threadIdx.x;
    const int g     = tid >> 7;          // group 0..1
    const int lane  = tid & 31;
    const int wig   = (tid >> 5) & 3;    // warp in group
    const int praw  = wig * 16 + (lane >> 1);   // row-pair index 0..63
    const int j     = lane & 1;                  // K-half 0/1
    const bool active = (praw < 50);
    const int pc    = active ? praw : 49;        // clamp for safe loads
    const int row0  = 2 * pc;
    const int own   = row0 + j;                  // row this thread finalizes
    const int bg0   = blockIdx.x * 4 + g * 2;    // first batch of this group
    const int bg1   = bg0 + 1;
    const int barid = 1 + g;

    // zero h buffers (h0 = 0; pad [100,128) stays 0 forever)
    for (int i = tid; i < 2 * 2 * 2 * PADH; i += BLOCK_T)
        ((float*)hbuf)[i] = 0.0f;

    // ---- W_hh: 2 rows x 52-col half -> 104 regs (shared by both batches) --
    unsigned long long w0[26], w1[26];
    {
        const ulonglong2* r0p =
            reinterpret_cast<const ulonglong2*>(W_hh + row0 * HDIM + KH * j);
        const ulonglong2* r1p =
            reinterpret_cast<const ulonglong2*>(W_hh + (row0 + 1) * HDIM + KH * j);
        #pragma unroll
        for (int k = 0; k < 13; k++) {
            ulonglong2 v = r0p[k];
            w0[2 * k] = v.x;  w0[2 * k + 1] = v.y;
        }
        #pragma unroll
        for (int k = 0; k < 12; k++) {
            ulonglong2 v = r1p[k];
            w1[2 * k] = v.x;  w1[2 * k + 1] = v.y;
        }
        // row 99's upper half, last pair: would read past W_hh; matching h
        // values are the zero pad, so zero weights are exact.
        if (pc == 49 && j == 1) {
            w1[24] = 0ull; w1[25] = 0ull;
        } else {
            ulonglong2 v = r1p[12];
            w1[24] = v.x; w1[25] = v.y;
        }
    }

    const float4 wih = *reinterpret_cast<const float4*>(W_ih + own * 4);

    const float4* xp0 = reinterpret_cast<const float4*>(x) + (size_t)bg0 * TLEN;
    const float4* xp1 = reinterpret_cast<const float4*>(x) + (size_t)bg1 * TLEN;
    __half* hs0 = Hs + (size_t)bg0 * TLEN * PADHS + own;
    __half* hs1 = Hs + (size_t)bg1 * TLEN * PADHS + own;

    __syncthreads();                     // init barrier (block-wide, once)

    // small phase offset between the two groups of this CTA (as in R8/R12)
    if (g == 1) {
        float d = 1.0f;
        #pragma unroll 1
        for (int k = 0; k < 64; k++)
            d = fmaf(d, 1.0000001f, 1e-7f);
        asm volatile("" :: "f"(d));
    }

    const float* hb0 = &hbuf[0][g][0][0];
    float*       hw0 = &hbuf[1][g][0][0];
    const float* hb1 = &hbuf[0][g][1][0];
    float*       hw1 = &hbuf[1][g][1][0];

    float4 xc0 = xp0[0];
    float4 xc1 = xp1[0];

    #pragma unroll 1
    for (int t = 0; t < TLEN; t++) {
        const int tn = (t < TLEN - 1) ? (t + 1) : t;
        float4 xn0 = xp0[tn];
        float4 xn1 = xp1[tn];

        // input projections (independent of h)
        float xpj0 = xc0.x * wih.x;
        xpj0 = fmaf(xc0.y, wih.y, xpj0);
        xpj0 = fmaf(xc0.z, wih.z, xpj0);
        xpj0 = fmaf(xc0.w, wih.w, xpj0);
        float xpj1 = xc1.x * wih.x;
        xpj1 = fmaf(xc1.y, wih.y, xpj1);
        xpj1 = fmaf(xc1.z, wih.z, xpj1);
        xpj1 = fmaf(xc1.w, wih.w, xpj1);

        // two interleaved matvecs over this thread's K-half
        unsigned long long a00 = 0ull, a01 = 0ull, a10 = 0ull, a11 = 0ull;
        unsigned long long b00 = 0ull, b01 = 0ull, b10 = 0ull, b11 = 0ull;
        const ulonglong2* hva =
            reinterpret_cast<const ulonglong2*>(hb0 + KH * j);
        const ulonglong2* hvb =
            reinterpret_cast<const ulonglong2*>(hb1 + KH * j);
        #pragma unroll
        for (int k = 0; k < 13; k++) {
            ulonglong2 ha  = hva[k];
            ulonglong2 hbv = hvb[k];
            a00 = ffma2(ha.x,  w0[2 * k],     a00);
            b00 = ffma2(hbv.x, w0[2 * k],     b00);
            a01 = ffma2(ha.y,  w0[2 * k + 1], a01);
            b01 = ffma2(hbv.y, w0[2 * k + 1], b01);
            a10 = ffma2(ha.x,  w1[2 * k],     a10);
            b10 = ffma2(hbv.x, w1[2 * k],     b10);
            a11 = ffma2(ha.y,  w1[2 * k + 1], a11);
            b11 = ffma2(hbv.y, w1[2 * k + 1], b11);
        }

        // half-dot sums; combine with partner lane (other K-half)
        float s00 = hsum2(fadd2(a00, a01));
        float s01 = hsum2(fadd2(a10, a11));
        float s10 = hsum2(fadd2(b00, b01));
        float s11 = hsum2(fadd2(b10, b11));
        float u00 = s00 + __shfl_xor_sync(0xFFFFFFFFu, s00, 1);
        float u01 = s01 + __shfl_xor_sync(0xFFFFFFFFu, s01, 1);
        float u10 = s10 + __shfl_xor_sync(0xFFFFFFFFu, s10, 1);
        float u11 = s11 + __shfl_xor_sync(0xFFFFFFFFu, s11, 1);

        const float hn0 = fast_tanh((j ? u01 : u00) + xpj0);
        const float hn1 = fast_tanh((j ? u11 : u10) + xpj1);

        if (active) {
            hw0[own] = hn0;                 // smem for the recurrence (fp32)
            hw1[own] = hn1;
            hs0[0] = __float2half_rn(hn0);  // fp16 trajectory (dead-end,
            hs1[0] = __float2half_rn(hn1);  //  pre-barrier: absorbed)
        }
        hs0 += PADHS;
        hs1 += PADHS;

        group_bar(barid);                   // h_{t+1} published for this group

        // swap read/write buffers; advance x
        const float* tp;
        tp = hb0; hb0 = hw0; hw0 = (float*)tp;
        tp = hb1; hb1 = hw1; hw1 = (float*)tp;
        xc0 = xn0;
        xc1 = xn1;
    }
}

// ============================================================================
// Kernel 2: out[b,t] = W_fc . h[b,t] + b_fc — R13 structure VERBATIM (48us).
// THREAD per output: 13 LDG.128 over the 208 B fp16 row (13-deep MLP),
// weights broadcast from smem, 8 parallel fp32 accumulators, no shuffles.
// ============================================================================
#define K2_BLOCK 256
#define K2_GRID  4096   // 4096 * 256 = 1,048,576 = 512 * 2048 outputs exactly

__global__ void __launch_bounds__(K2_BLOCK)
proj_kernel(const float* __restrict__ W_fc,   // [1, 100]
            const float* __restrict__ b_fc,   // [1]
            float* __restrict__ out)          // [512*2048]
{
    // weights as 104 floats (pad [100,104) = 0): 26 float4 broadcasts
    __shared__ __align__(16) float wsm[PADHS];
    {
        const int tt = threadIdx.x;
        if (tt < PADHS)
            wsm[tt] = (tt < HDIM) ? W_fc[tt] : 0.0f;
    }
    __syncthreads();

    const int bt = blockIdx.x * K2_BLOCK + threadIdx.x;   // one output/thread
    const float bias = b_fc[0];

    const uint4* hp = reinterpret_cast<const uint4*>(Hs + (size_t)bt * PADHS);
    const float4* wp = reinterpret_cast<const float4*>(wsm);

    float acc0 = 0.f, acc1 = 0.f, acc2 = 0.f, acc3 = 0.f;
    float acc4 = 0.f, acc5 = 0.f, acc6 = 0.f, acc7 = 0.f;

    #pragma unroll
    for (int k = 0; k < 13; k++) {
        uint4 v = hp[k];                        // 8 fp16 values
        float4 wa = wp[2 * k];
        float4 wb = wp[2 * k + 1];
        float2 f0 = __half22float2(*reinterpret_cast<const __half2*>(&v.x));
        float2 f1 = __half22float2(*reinterpret_cast<const __half2*>(&v.y));
        float2 f2 = __half22float2(*reinterpret_cast<const __half2*>(&v.z));
        float2 f3 = __half22float2(*reinterpret_cast<const __half2*>(&v.w));
        acc0 = fmaf(f0.x, wa.x, acc0);
        acc1 = fmaf(f0.y, wa.y, acc1);
        acc2 = fmaf(f1.x, wa.z, acc2);
        acc3 = fmaf(f1.y, wa.w, acc3);
        acc4 = fmaf(f2.x, wb.x, acc4);
        acc5 = fmaf(f2.y, wb.y, acc5);
        acc6 = fmaf(f3.x, wb.z, acc6);
        acc7 = fmaf(f3.y, wb.w, acc7);
    }

    const float s = ((acc0 + acc1) + (acc2 + acc3)) +
                    ((acc4 + acc5) + (acc6 + acc7));
    out[bt] = s + bias;
}

extern "C" void kernel_launch(void* const* d_in, const int* in_sizes, int n_in,
                              void* d_out, int out_size) {
    const float* x    = (const float*)d_in[0];  // [512,2048,4]
    const float* W_ih = (const float*)d_in[1];  // [100,4]
    const float* W_hh = (const float*)d_in[2];  // [100,100]
    const float* W_fc = (const float*)d_in[3];  // [1,100]
    const float* b_fc = (const float*)d_in[4];  // [1]
    float* out = (float*)d_out;                 // [512,2048,1]

    crnn_step_kernel<<<NBLOCKS, BLOCK_T>>>(x, W_ih, W_hh);
    proj_kernel<<<K2_GRID, K2_BLOCK>>>(W_fc, b_fc, out);
}